// round 5
// baseline (speedup 1.0000x reference)
#include <cuda_runtime.h>
#include <stdint.h>

#define Bn 16384
#define Tn 256
#define Dn 8
#define Fn 512
#define Cn 16
#define Ln 256

#define TTILES 16            // tree tiles (16 trees each)
#define BTILES 16            // sample tiles (1024 samples each)
#define BTILE  1024

// ---------------- device scratch (static, no runtime allocation) ------------
__device__ unsigned short g_fidx16[Tn * Dn];                 // 4 KB
__device__ unsigned char  g_dec[(size_t)Tn * Bn];            // 4 MB, layout [T][B]
__device__ float          g_part[(size_t)TTILES * Bn * Cn];  // 16 MB partials
__device__ int            g_scratch[16];

// ---------------- kernel 1: argmax over F per (tree, depth) -----------------
// one warp per (t,d); all 16 strided loads batched before comparing.
__global__ void k_argmax(const float* __restrict__ fw) {
    int g    = blockIdx.x * 8 + (threadIdx.x >> 5);   // 2048 warps total
    int lane = threadIdx.x & 31;
    const float* p = fw + (size_t)g * Fn;

    float v[16];
    #pragma unroll
    for (int i = 0; i < 16; i++) v[i] = p[lane + (i << 5)];

    float best = v[0];
    int   bi   = lane;
    #pragma unroll
    for (int i = 1; i < 16; i++)
        if (v[i] > best) { best = v[i]; bi = lane + (i << 5); }

    #pragma unroll
    for (int off = 16; off; off >>= 1) {
        float ov = __shfl_down_sync(0xffffffffu, best, off);
        int   oi = __shfl_down_sync(0xffffffffu, bi,   off);
        if (ov > best || (ov == best && oi < bi)) { best = ov; bi = oi; }
    }
    if (lane == 0) g_fidx16[g] = (unsigned short)bi;
}

// ---------------- kernel 2: per-(sample,tree) decision byte -----------------
// round-2 version (best measured): 512 blocks of 32 samples, 512 threads =
// 16 warps, each warp owns 16 trees. x rows in smem stride 513 ->
// conflict-free gathers. Output tree-major, coalesced 32B warp stores.
__global__ __launch_bounds__(512) void k_decide(const float* __restrict__ x,
                                                const float* __restrict__ thr) {
    extern __shared__ float smem[];
    float* s_x   = smem;                                   // 32 * 513 floats
    uint4* s_fpk = (uint4*)(smem + 32 * 513);              // 256 * 16 B
    float* s_thr = (float*)(s_fpk + Tn);                   // 2048 floats

    int tid = threadIdx.x;
    int b0  = blockIdx.x * 32;

    const float4* xg = (const float4*)x + (size_t)b0 * (Fn / 4);
    for (int i = tid; i < 32 * (Fn / 4); i += 512) {
        float4 v = xg[i];
        int row = i >> 7, c4 = i & 127;
        float* dst = s_x + row * 513 + c4 * 4;
        dst[0] = v.x; dst[1] = v.y; dst[2] = v.z; dst[3] = v.w;
    }
    for (int i = tid; i < (Tn * Dn) / 2; i += 512)
        ((unsigned*)s_fpk)[i] = ((const unsigned*)g_fidx16)[i];
    for (int i = tid; i < Tn * Dn; i += 512)
        s_thr[i] = thr[i];
    __syncthreads();

    int warp = tid >> 5, lane = tid & 31;
    const float* xr = s_x + lane * 513;

    #pragma unroll 4
    for (int tt = 0; tt < 16; tt++) {
        int t = warp * 16 + tt;
        uint4 fp = s_fpk[t];
        const float4* th = (const float4*)(s_thr + t * 8);
        float4 t0 = th[0], t1 = th[1];
        unsigned dec = 0;
        dec = (dec << 1) | (unsigned)(xr[fp.x & 0xFFFFu] > t0.x);
        dec = (dec << 1) | (unsigned)(xr[fp.x >> 16]     > t0.y);
        dec = (dec << 1) | (unsigned)(xr[fp.y & 0xFFFFu] > t0.z);
        dec = (dec << 1) | (unsigned)(xr[fp.y >> 16]     > t0.w);
        dec = (dec << 1) | (unsigned)(xr[fp.z & 0xFFFFu] > t1.x);
        dec = (dec << 1) | (unsigned)(xr[fp.z >> 16]     > t1.y);
        dec = (dec << 1) | (unsigned)(xr[fp.w & 0xFFFFu] > t1.z);
        dec = (dec << 1) | (unsigned)(xr[fp.w >> 16]     > t1.w);
        g_dec[(size_t)t * Bn + b0 + lane] = (unsigned char)dec;
    }
}

// ---------------- launch-slot shim (makes k_accum the 4th user launch) ------
__global__ void k_tiny() { if (threadIdx.x < 16) g_scratch[threadIdx.x] = 0; }

// ---------------- kernel 3: leaf gather, double-buffered staging ------------
__global__ __launch_bounds__(512) void k_accum(const float* __restrict__ resp) {
    extern __shared__ float4 dynsmem[];
    float4*   s_r  = dynsmem;                            // 2 * Ln*8 float4
    unsigned* s_du = (unsigned*)(dynsmem + 2 * Ln * 8);  // 2 * 256 u32

    int tid   = threadIdx.x;
    int b0    = blockIdx.x * BTILE;
    int tbase = blockIdx.y * (Tn / TTILES);

    float4 a[8];
    #pragma unroll
    for (int k = 0; k < 8; k++) a[k] = make_float4(0.f, 0.f, 0.f, 0.f);

    {
        const float4* rs = (const float4*)resp + (size_t)tbase * (Ln * Cn / 4);
        #pragma unroll
        for (int j = 0; j < 2; j++) {
            int i = tid + j * 512;
            float4 v = rs[i];
            int d = i >> 2, k = i & 3;
            s_r[d * 8 + ((k + 5 * d) & 7)] = v;
        }
        if (tid < BTILE / 4)
            s_du[tid] = ((const unsigned*)(g_dec + (size_t)tbase * Bn + b0))[tid];
    }
    __syncthreads();

    for (int tt = 0; tt < Tn / TTILES; tt++) {
        int cur = tt & 1;
        float4 nv0, nv1; unsigned ndu = 0;
        bool have = (tt + 1 < Tn / TTILES);
        if (have) {
            int t = tbase + tt + 1;
            const float4* rs = (const float4*)resp + (size_t)t * (Ln * Cn / 4);
            nv0 = rs[tid];
            nv1 = rs[tid + 512];
            if (tid < BTILE / 4)
                ndu = ((const unsigned*)(g_dec + (size_t)t * Bn + b0))[tid];
        }

        const unsigned char* sd = (const unsigned char*)(s_du + cur * (BTILE / 4));
        const float4* sr = s_r + cur * (Ln * 8);
        int d0 = sd[tid];
        int d1 = sd[tid + 512];
        const float4* r0 = sr + d0 * 8; int o0 = (5 * d0) & 7;
        const float4* r1 = sr + d1 * 8; int o1 = (5 * d1) & 7;
        #pragma unroll
        for (int k = 0; k < 4; k++) {
            float4 v0 = r0[(k + o0) & 7];
            a[k].x += v0.x; a[k].y += v0.y; a[k].z += v0.z; a[k].w += v0.w;
            float4 v1 = r1[(k + o1) & 7];
            a[4 + k].x += v1.x; a[4 + k].y += v1.y;
            a[4 + k].z += v1.z; a[4 + k].w += v1.w;
        }

        if (have) {
            int nb = cur ^ 1;
            float4* dr = s_r + nb * (Ln * 8);
            { int i = tid;       int d = i >> 2, k = i & 3; dr[d * 8 + ((k + 5 * d) & 7)] = nv0; }
            { int i = tid + 512; int d = i >> 2, k = i & 3; dr[d * 8 + ((k + 5 * d) & 7)] = nv1; }
            if (tid < BTILE / 4) s_du[nb * (BTILE / 4) + tid] = ndu;
        }
        __syncthreads();
    }

    float4* p0 = (float4*)(g_part + ((size_t)blockIdx.y * Bn + b0 + tid) * Cn);
    float4* p1 = (float4*)(g_part + ((size_t)blockIdx.y * Bn + b0 + 512 + tid) * Cn);
    #pragma unroll
    for (int k = 0; k < 4; k++) { p0[k] = a[k]; p1[k] = a[4 + k]; }
}

// ---------------- kernel 4: reduce partials across tree tiles ---------------
// 4 independent float4 accumulator chains (tt = 4m+j for chain j) -> ptxas
// cannot collapse them into one serial chain; ~4 loads in flight per thread.
__global__ __launch_bounds__(256) void k_reduce(float* __restrict__ out) {
    int i = blockIdx.x * 256 + threadIdx.x;       // float4 index, 65536 total
    const float4* p = (const float4*)g_part;
    const size_t S = (size_t)Bn * Cn / 4;         // tile stride in float4

    float4 a0 = make_float4(0.f, 0.f, 0.f, 0.f);
    float4 a1 = a0, a2 = a0, a3 = a0;
    #pragma unroll
    for (int m = 0; m < 4; m++) {
        float4 v0 = p[(size_t)(4 * m + 0) * S + i];
        float4 v1 = p[(size_t)(4 * m + 1) * S + i];
        float4 v2 = p[(size_t)(4 * m + 2) * S + i];
        float4 v3 = p[(size_t)(4 * m + 3) * S + i];
        a0.x += v0.x; a0.y += v0.y; a0.z += v0.z; a0.w += v0.w;
        a1.x += v1.x; a1.y += v1.y; a1.z += v1.z; a1.w += v1.w;
        a2.x += v2.x; a2.y += v2.y; a2.z += v2.z; a2.w += v2.w;
        a3.x += v3.x; a3.y += v3.y; a3.z += v3.z; a3.w += v3.w;
    }
    const float sc = 1.0f / (float)Tn;
    float4 s;
    s.x = ((a0.x + a1.x) + (a2.x + a3.x)) * sc;
    s.y = ((a0.y + a1.y) + (a2.y + a3.y)) * sc;
    s.z = ((a0.z + a1.z) + (a2.z + a3.z)) * sc;
    s.w = ((a0.w + a1.w) + (a2.w + a3.w)) * sc;
    ((float4*)out)[i] = s;
}

// ---------------- launch -----------------------------------------------------
extern "C" void kernel_launch(void* const* d_in, const int* in_sizes, int n_in,
                              void* d_out, int out_size) {
    const float* x    = (const float*)d_in[0];   // (B, F)
    const float* fw   = (const float*)d_in[1];   // (T, D, F)
    const float* thr  = (const float*)d_in[2];   // (T, D)
    const float* resp = (const float*)d_in[3];   // (T, L, C)
    float* out = (float*)d_out;                  // (B, C)

    const int smem_dec = 32 * 513 * 4 + Tn * 16 + Tn * Dn * 4;     // 77952 B
    const int smem_acc = 2 * Ln * 8 * 16 + 2 * (BTILE / 4) * 4;    // 67584 B
    cudaFuncSetAttribute(k_decide, cudaFuncAttributeMaxDynamicSharedMemorySize,
                         smem_dec);
    cudaFuncSetAttribute(k_accum, cudaFuncAttributeMaxDynamicSharedMemorySize,
                         smem_acc);
    (void)in_sizes; (void)n_in; (void)out_size;

    k_argmax<<<(Tn * Dn) / 8, 256>>>(fw);                      // launch 1
    k_decide<<<Bn / 32, 512, smem_dec>>>(x, thr);              // launch 2
    k_tiny<<<1, 32>>>();                                       // launch 3 (shim)
    k_accum<<<dim3(BTILES, TTILES), 512, smem_acc>>>(resp);    // launch 4 <- ncu
    k_reduce<<<(Bn * Cn / 4) / 256, 256>>>(out);               // launch 5
}